// round 16
// baseline (speedup 1.0000x reference)
#include <cuda_runtime.h>
#include <cuda_fp16.h>
#include <cmath>
#include <cstdint>

#define BB 2
#define C 64
#define H 64
#define W 64
#define L 4096   // H*W
#define F 576    // C*9
#define HP 66    // H+2

#define NCH 36                    // 576/16 k16-chunks
#define NBLK 64                   // 64 key/query blocks of 64
#define NTASKP 1056               // pair-tasks: sum_i (32 - (i>>1))

#define ROWP 48                   // 32B data + 16B pad: conflict-free LDSM
#define ABYTES (64*ROWP)          // 3072
#define BBYTES (128*ROWP)         // 6144
#define STAGE (2*ABYTES + 2*BBYTES)  // 18432 (A-s0, A-s1, B-s0, B-s1)
#define NSTG 4
#define SMEM_REQ (NSTG*STAGE)     // 73728 -> 2 CTAs/SM (16 warps/SM)

// ---------------- scratch ----------------
__device__ float g_xcl[BB*HP*HP*C];      // [b][y][x][c] channels-last reflect-padded
__device__ float g_n2[BB*HP*HP];         // per-pixel channel sum of squares
__device__ float g_h1[BB*C*L];
__device__ float g_feat[BB*C*L];
__device__ float g_rnorm[BB*L];
__device__ __half g_p0[BB*L*F];          // [b][q][f'] fp16 split hi (f' = k*64+c)
__device__ __half g_p1[BB*L*F];          // fp16 split lo
__device__ float g_pv[BB*NBLK*3*L];      // partial top-3 values: [b][slot][e][q]
__device__ int   g_pi[BB*NBLK*3*L];      // partial top-3 indices
__device__ float g_tv[BB*L*3];
__device__ int   g_ti[BB*L*3];
__device__ float g_Tcat[BB*2*C*L];
__device__ float g_wc[64*256];           // combined final weights
__device__ float g_bc[64];               // combined final bias

// ---------------- PTX helpers (baseline ISA) ----------------
__device__ __forceinline__ uint32_t s2u(const void* p) {
    uint32_t a;
    asm("{ .reg .u64 t; cvta.to.shared.u64 t, %1; cvt.u32.u64 %0, t; }" : "=r"(a) : "l"(p));
    return a;
}
#define CPA16(d, s) asm volatile("cp.async.cg.shared.global [%0], [%1], 16;" :: "r"(d), "l"(s))
#define CPCOMMIT()  asm volatile("cp.async.commit_group;" ::: "memory")
#define CPWAIT2()   asm volatile("cp.async.wait_group 2;" ::: "memory")
#define CPWAIT1()   asm volatile("cp.async.wait_group 1;" ::: "memory")
#define CPWAIT0()   asm volatile("cp.async.wait_group 0;" ::: "memory")
#define LDSM_X4(r, addr) asm volatile("ldmatrix.sync.aligned.m8n8.x4.shared.b16 {%0,%1,%2,%3}, [%4];" \
    : "=r"((r)[0]), "=r"((r)[1]), "=r"((r)[2]), "=r"((r)[3]) : "r"(addr))
#define MMAF16(c, a, b0, b1) \
    asm volatile("mma.sync.aligned.m16n8k16.row.col.f32.f16.f16.f32 " \
        "{%0,%1,%2,%3}, {%4,%5,%6,%7}, {%8,%9}, {%0,%1,%2,%3};" \
        : "+f"((c)[0]), "+f"((c)[1]), "+f"((c)[2]), "+f"((c)[3]) \
        : "r"((a)[0]), "r"((a)[1]), "r"((a)[2]), "r"((a)[3]), "r"(b0), "r"(b1))

// total order: larger value first, ties -> smaller index (lax.top_k)
__device__ __forceinline__ bool bet(float va, int ia, float vb, int ib) {
    return (va > vb) || (va == vb && ia < ib);
}
__device__ __forceinline__ void ins3(float v, int i,
                                     float& v0, int& i0, float& v1, int& i1,
                                     float& v2, int& i2) {
    if (bet(v, i, v2, i2)) {
        if (bet(v, i, v0, i0))      { v2=v1;i2=i1; v1=v0;i1=i0; v0=v;i0=i; }
        else if (bet(v, i, v1, i1)) { v2=v1;i2=i1; v1=v;i1=i; }
        else                        { v2=v;i2=i; }
    }
}

// ---------------- reflect pad (channels-last) ----------------
__global__ void k_xpad(const float* __restrict__ x) {
    int idx = blockIdx.x * blockDim.x + threadIdx.x;
    const int total = BB*C*HP*HP;
    if (idx >= total) return;
    int xx = idx % HP; int t = idx / HP;
    int yy = t % HP;   t /= HP;
    int c  = t % C;    int b = t / C;
    int sy = yy - 1; sy = sy < 0 ? -sy : (sy > H-1 ? 2*(H-1)-sy : sy);
    int sx = xx - 1; sx = sx < 0 ? -sx : (sx > W-1 ? 2*(W-1)-sx : sx);
    g_xcl[((b*HP + yy)*HP + xx)*C + c] = x[((b*C + c)*H + sy)*W + sx];
}

// ---------------- per-pixel channel sum-of-squares (8 lanes per pixel) ----------------
__global__ void k_n2() {
    int idx = blockIdx.x * blockDim.x + threadIdx.x;
    if (idx >= BB*HP*HP*8) return;
    int pix = idx >> 3, l8 = idx & 7;
    const float4* p = (const float4*)(g_xcl + (size_t)pix*C + l8*8);
    float4 a = p[0], c = p[1];
    float s = a.x*a.x + a.y*a.y + a.z*a.z + a.w*a.w
            + c.x*c.x + c.y*c.y + c.z*c.z + c.w*c.w;
    s += __shfl_xor_sync(0xffffffffu, s, 1);
    s += __shfl_xor_sync(0xffffffffu, s, 2);
    s += __shfl_xor_sync(0xffffffffu, s, 4);
    if (l8 == 0) g_n2[pix] = s;
}

// ---------------- patch rnorm from 3x3 window of n2 ----------------
__global__ void k_rnorm() {
    int idx = blockIdx.x * blockDim.x + threadIdx.x;
    if (idx >= BB*L) return;
    int b = idx / L, q = idx % L;
    int qy = q >> 6, qx = q & 63;
    const float* n2 = g_n2 + b*HP*HP;
    float s = 0.f;
    #pragma unroll
    for (int i = 0; i < 3; i++)
        #pragma unroll
        for (int j = 0; j < 3; j++)
            s += n2[(qy + i)*HP + qx + j];
    g_rnorm[idx] = 1.f / fmaxf(sqrtf(s), 1e-12f);
}

// ---------------- normalized unfold, fp16 2-way split, half2-vectorized ----------------
__global__ void k_unsplit() {
    int idx = blockIdx.x * blockDim.x + threadIdx.x;
    if (idx >= BB*L*(F/2)) return;
    int f2 = idx % (F/2); int t = idx / (F/2);
    int q = t % L;        int b = t / L;
    int f = f2 * 2;
    int k = f >> 6, c = f & 63;       // c even; c,c+1 share k
    int i = k / 3, j = k % 3;
    int qy = q >> 6, qx = q & 63;
    float rn = g_rnorm[b*L + q];
    const float2 xv = *(const float2*)(g_xcl + ((size_t)((b*HP + qy + i)*HP + qx + j))*C + c);
    float va = xv.x * rn, vb = xv.y * rn;
    __half ha0 = __float2half_rn(va), hb0 = __float2half_rn(vb);
    __half ha1 = __float2half_rn(va - __half2float(ha0));
    __half hb1 = __float2half_rn(vb - __half2float(hb0));
    size_t o = (size_t)b*L*F + (size_t)q*F + f;
    *(__half2*)(g_p0 + o) = __halves2half2(ha0, hb0);
    *(__half2*)(g_p1 + o) = __halves2half2(ha1, hb1);
}

// ---------------- symmetric fp16 HMMA Gram: 64 x 128 tile per CTA (col pair) ----------------
// grid (1056, BB), 256 threads (8 warps, 2x4), 2 CTAs/SM, k16 chunks, 4-stage pipeline.
__global__ void __launch_bounds__(256, 2) k_gram_sym() {
    extern __shared__ char smem[];
    const uint32_t sb = s2u(smem);

    const int tid = threadIdx.x;
    const int w = tid >> 5, lane = tid & 31;
    const int b = blockIdx.y;

    // decode task -> (i, jp): row-block i, column pair jp (cols 2jp, 2jp+1), 2jp+1 >= i
    int i = 0, jp = 0;
    {
        int t = blockIdx.x, base = 0;
        for (;;) {
            int cnt = 32 - (i >> 1);
            if (t < base + cnt) { jp = (i >> 1) + (t - base); break; }
            base += cnt; i++;
        }
    }
    const int q0 = i * 64;
    const int n0 = jp * 128;
    const int j0 = 2*jp;

    const __half* P0 = g_p0 + (size_t)b*L*F;
    const __half* P1 = g_p1 + (size_t)b*L*F;

    const int warpRow = (w >> 2) * 32;   // 0 or 32
    const int warpCol = (w & 3) * 32;    // 0,32,64,96
    const uint32_t aofs = (uint32_t)((warpRow + (lane & 15))*ROWP + (lane >> 4)*16);
    // bofs is relative to the B region start (call site adds 2*ABYTES + sp*BBYTES)
    const uint32_t bofs = (uint32_t)((warpCol + ((lane >> 4) & 1)*8 + (lane & 7))*ROWP
                          + ((lane >> 3) & 1)*16);

    // hoisted loader: 768 granules (384 rows x 2 x 16B), 3 per thread
    const __half* lsrc[3];
    uint32_t ldst[3];
    #pragma unroll
    for (int t3 = 0; t3 < 3; t3++) {
        int g = t3*256 + tid;
        int rr = g >> 1, c = g & 1;
        int grow; const __half* base_;
        if (rr < 128) { base_ = (rr >= 64) ? P1 : P0; grow = q0 + (rr & 63); }
        else          { int rb = rr - 128; base_ = (rb >= 128) ? P1 : P0; grow = n0 + (rb & 127); }
        lsrc[t3] = base_ + (size_t)grow*F + c*8;
        ldst[t3] = (uint32_t)(rr*ROWP + c*16);
    }

    float acc[2][4][4];
    #pragma unroll
    for (int mf = 0; mf < 2; mf++)
        #pragma unroll
        for (int nf = 0; nf < 4; nf++)
            #pragma unroll
            for (int e = 0; e < 4; e++) acc[mf][nf][e] = 0.f;

    #define ISSUE(pc) do {                                                      \
        int _f0 = (pc) * 16;                                                    \
        uint32_t _st = sb + ((pc) & 3) * STAGE;                                 \
        CPA16(_st + ldst[0], lsrc[0] + _f0);                                    \
        CPA16(_st + ldst[1], lsrc[1] + _f0);                                    \
        CPA16(_st + ldst[2], lsrc[2] + _f0);                                    \
        CPCOMMIT();                                                             \
    } while (0)

    ISSUE(0); ISSUE(1); ISSUE(2);

    for (int ck = 0; ck < NCH; ck++) {
        if (ck < NCH-2)       { CPWAIT2(); }
        else if (ck == NCH-2) { CPWAIT1(); }
        else                  { CPWAIT0(); }
        __syncthreads();
        if (ck + 3 < NCH) ISSUE(ck + 3);

        const uint32_t stage = sb + (ck & 3) * STAGE;

        // load ALL fragments first (identical per-warp pattern to 64x64 kernel)
        uint32_t afr[2][2][4];   // [split][mf]
        #pragma unroll
        for (int sp = 0; sp < 2; sp++)
            #pragma unroll
            for (int mf = 0; mf < 2; mf++)
                LDSM_X4(afr[sp][mf], stage + sp*ABYTES + aofs + mf*(16*ROWP));
        uint32_t bfr[2][2][4];   // [split][nfp]
        #pragma unroll
        for (int sp = 0; sp < 2; sp++)
            #pragma unroll
            for (int nfp = 0; nfp < 2; nfp++)
                LDSM_X4(bfr[sp][nfp], stage + 2*ABYTES + sp*BBYTES + bofs + nfp*(16*ROWP));

        // 3 split-term passes over all 8 distinct accumulators
        #pragma unroll
        for (int mf = 0; mf < 2; mf++)
            #pragma unroll
            for (int nfp = 0; nfp < 2; nfp++)
                #pragma unroll
                for (int nn = 0; nn < 2; nn++)
                    MMAF16(acc[mf][nfp*2+nn], afr[0][mf], bfr[0][nfp][nn*2], bfr[0][nfp][nn*2+1]);
        #pragma unroll
        for (int mf = 0; mf < 2; mf++)
            #pragma unroll
            for (int nfp = 0; nfp < 2; nfp++)
                #pragma unroll
                for (int nn = 0; nn < 2; nn++)
                    MMAF16(acc[mf][nfp*2+nn], afr[1][mf], bfr[0][nfp][nn*2], bfr[0][nfp][nn*2+1]);
        #pragma unroll
        for (int mf = 0; mf < 2; mf++)
            #pragma unroll
            for (int nfp = 0; nfp < 2; nfp++)
                #pragma unroll
                for (int nn = 0; nn < 2; nn++)
                    MMAF16(acc[mf][nfp*2+nn], afr[0][mf], bfr[1][nfp][nn*2], bfr[1][nfp][nn*2+1]);
    }
    #undef ISSUE

    // ---- epilogue: tile -> smem [64][129], fold rows + cols ----
    float* Ct = (float*)smem;    // 64*129*4 = 33024 B, aliases stages (cp.async drained)
    __syncthreads();
    #pragma unroll
    for (int mf = 0; mf < 2; mf++)
        #pragma unroll
        for (int nf = 0; nf < 4; nf++)
            #pragma unroll
            for (int e = 0; e < 4; e++) {
                int r = warpRow + mf*16 + (e >> 1)*8 + (lane >> 2);
                int c = warpCol + nf*8 + (lane & 3)*2 + (e & 1);
                Ct[r*129 + c] = acc[mf][nf][e];
            }
    __syncthreads();

    // row-fold: threads 0-63, queries block i, two key halves -> slots j0, j0+1 (when >= i)
    if (tid < 64) {
        int r = tid;
        #pragma unroll
        for (int h = 0; h < 2; h++) {
            int jh = j0 + h;
            if (jh >= i) {
                float v0=-2.f, v1=-2.f, v2=-2.f;
                int   i0=0x7fffffff, i1=0x7fffffff, i2=0x7fffffff;
                int cb = n0 + h*64;
                #pragma unroll 8
                for (int c = 0; c < 64; c++)
                    ins3(Ct[r*129 + h*64 + c], cb + c, v0,i0, v1,i1, v2,i2);
                size_t base = ((size_t)(b*NBLK + jh)*3)*L + (q0 + r);
                g_pv[base]       = v0; g_pv[base + L]   = v1; g_pv[base + 2*L] = v2;
                g_pi[base]       = i0; g_pi[base + L]   = i1; g_pi[base + 2*L] = i2;
            }
        }
    } else if (tid < 192) {
        // col-fold: queries block j0 + (c>>6) strictly > i, keys block i -> slot i
        int c = tid - 64;
        int qb = j0 + (c >> 6);
        if (qb > i) {
            float v0=-2.f, v1=-2.f, v2=-2.f;
            int   i0=0x7fffffff, i1=0x7fffffff, i2=0x7fffffff;
            #pragma unroll 8
            for (int r = 0; r < 64; r++)
                ins3(Ct[r*129 + c], q0 + r, v0,i0, v1,i1, v2,i2);
            size_t base = ((size_t)(b*NBLK + i)*3)*L + (qb*64 + (c & 63));
            g_pv[base]       = v0; g_pv[base + L]   = v1; g_pv[base + 2*L] = v2;
            g_pi[base]       = i0; g_pi[base + L]   = i1; g_pi[base + 2*L] = i2;
        }
    }
}

// ---------------- merge the 64 per-block partial top-3s (8 threads/query) ----------------
__global__ void __launch_bounds__(256) k_merge64() {
    __shared__ float sv[8*32*3];
    __shared__ int   si[8*32*3];
    int tid = threadIdx.x;
    int qloc = tid & 31, g = tid >> 5;
    int qg = blockIdx.x*32 + qloc;          // 0 .. BB*L-1
    int b = qg / L, q = qg % L;

    float v0 = -2.f, v1 = -2.f, v2 = -2.f;
    int   i0 = 0x7fffffff, i1 = 0x7fffffff, i2 = 0x7fffffff;
    #pragma unroll
    for (int s8 = 0; s8 < 8; s8++) {
        int s = g*8 + s8;
        size_t base = ((size_t)(b*NBLK + s)*3)*L + q;
        float a0 = g_pv[base]; int j0 = g_pi[base];
        if (bet(a0, j0, v2, i2)) {          // partials sorted desc -> short-circuit
            ins3(a0, j0, v0,i0, v1,i1, v2,i2);
            ins3(g_pv[base + L],   g_pi[base + L],   v0,i0, v1,i1, v2,i2);
            ins3(g_pv[base + 2*L], g_pi[base + 2*L], v0,i0, v1,i1, v2,i2);
        }
    }
    int sidx = (g*32 + qloc)*3;
    sv[sidx] = v0; sv[sidx+1] = v1; sv[sidx+2] = v2;
    si[sidx] = i0; si[sidx+1] = i1; si[sidx+2] = i2;
    __syncthreads();
    if (g == 0) {
        #pragma unroll
        for (int gg = 1; gg < 8; gg++) {
            int s2 = (gg*32 + qloc)*3;
            float a0 = sv[s2]; int j0 = si[s2];
            if (bet(a0, j0, v2, i2)) {
                ins3(a0, j0, v0,i0, v1,i1, v2,i2);
                ins3(sv[s2+1], si[s2+1], v0,i0, v1,i1, v2,i2);
                ins3(sv[s2+2], si[s2+2], v0,i0, v1,i1, v2,i2);
            }
        }
        size_t d = (size_t)(b*L + q)*3;
        g_tv[d]   = v0; g_tv[d+1] = v1; g_tv[d+2] = v2;
        g_ti[d]   = i0; g_ti[d+1] = i1; g_ti[d+2] = i2;
    }
}

// ---------------- 3x3 conv (zero pad), optional relu ----------------
__global__ void __launch_bounds__(256) k_conv3x3(
    const float* __restrict__ xin, const float* __restrict__ w,
    const float* __restrict__ bias, int relu, int insel, int outsel)
{
    __shared__ float s_in[16][324];
    __shared__ float s_w[16][144];

    const float* in = insel ? g_h1 : xin;
    float* out = outsel ? g_feat : g_h1;

    int tile = blockIdx.x;
    int oc0  = blockIdx.y * 16;
    int b    = blockIdx.z;
    int ty0 = (tile / 4) * 16, tx0 = (tile % 4) * 16;
    int tid = threadIdx.x;
    int py = tid / 16, px = tid % 16;

    float acc[16];
    #pragma unroll
    for (int o = 0; o < 16; o++) acc[o] = bias[oc0 + o];

    for (int icc = 0; icc < 4; icc++) {
        for (int i = tid; i < 16*324; i += 256) {
            int ic = i / 324; int rem = i % 324;
            int yy = rem / 18, xx = rem % 18;
            int gy = ty0 + yy - 1, gx = tx0 + xx - 1;
            float v = 0.f;
            if (gy >= 0 && gy < H && gx >= 0 && gx < W)
                v = in[((b*C + icc*16 + ic)*H + gy)*W + gx];
            s_in[ic][rem] = v;
        }
        for (int i = tid; i < 16*144; i += 256) {
            int o = i / 144; int rem = i % 144;
            s_w[o][rem] = w[((oc0 + o)*C + icc*16 + rem/9)*9 + rem%9];
        }
        __syncthreads();

        for (int ic = 0; ic < 16; ic++) {
            float v[9];
            #pragma unroll
            for (int dy = 0; dy < 3; dy++)
                #pragma unroll
                for (int dx = 0; dx < 3; dx++)
                    v[dy*3+dx] = s_in[ic][(py+dy)*18 + px+dx];
            #pragma unroll
            for (int o = 0; o < 16; o++) {
                float a = acc[o];
                #pragma unroll
                for (int k = 0; k < 9; k++) a += v[k] * s_w[o][ic*9 + k];
                acc[o] = a;
            }
        }
        __syncthreads();
    }
    int gy = ty0 + py, gx = tx0 + px;
    #pragma unroll
    for (int o = 0; o < 16; o++) {
        float v = acc[o];
        if (relu) v = fmaxf(v, 0.f);
        out[((b*C + oc0 + o)*H + gy)*W + gx] = v;
    }
}

// ---------------- gather + fold3 + scale (coalesced writes via smem) ----------------
__global__ void __launch_bounds__(256) k_fold() {
    __shared__ float st[64*128];    // [c][px], 32 KB
    int tile = blockIdx.x;
    int tt   = blockIdx.y;
    int b    = blockIdx.z;
    int tid  = threadIdx.x;
    int p = tid & 127, ch0 = (tid >> 7) * 32;
    int y = tile*2 + (p >> 6), x = p & 63;
    int q = y*W + x;
    int slot = tt + 1;

    float S = g_tv[(b*L + q)*3 + slot];
    const int bbase = b*HP*HP;

    int off[9];
    #pragma unroll
    for (int i = 0; i < 3; i++) {
        #pragma unroll
        for (int j = 0; j < 3; j++) {
            int h = y + 1 - i, w = x + 1 - j;
            int o = -1;
            if (h >= 0 && h < H && w >= 0 && w < W) {
                int r = g_ti[(b*L + h*W + w)*3 + slot];
                int ry = r >> 6, rx = r & 63;
                o = (bbase + (ry + i)*HP + (rx + j)) * C + ch0;
            }
            off[i*3 + j] = o;
        }
    }

    float4 a4[8];
    #pragma unroll
    for (int r = 0; r < 8; r++) a4[r] = make_float4(0.f, 0.f, 0.f, 0.f);
    #pragma unroll
    for (int k = 0; k < 9; k++) {
        if (off[k] >= 0) {
            const float4* src = (const float4*)(g_xcl + off[k]);
            #pragma unroll
            for (int r = 0; r < 8; r++) {
                float4 v = src[r];
                a4[r].x += v.x; a4[r].y += v.y; a4[r].z += v.z; a4[r].w += v.w;
            }
        }
    }
    float scale = S * (1.f/9.f);
    #pragma unroll
    for (int r = 0; r < 8; r++) {
        st[(ch0 + r*4 + 0)*128 + p] = a4[r].x * scale;
        st[(ch0 + r*4 + 1)*128 + p] = a4[r].y * scale;
        st[(ch0 + r*4 + 2)*128 + p] = a4[r].z * scale;
        st[(ch0 + r*4 + 3)*128 + p] = a4[r].w * scale;
    }
    __syncthreads();
    float* out = &g_Tcat[(size_t)((b*2 + tt)*C)*L + tile*128];
    #pragma unroll
    for (int it = 0; it < 32; it++) {
        int idx2 = it*256 + tid;
        int c = idx2 >> 7, px = idx2 & 127;
        out[(size_t)c*L + px] = st[idx2];
    }
}

// ---------------- fold wt1 into wt2: wc = [wt2_f | wt2_x | wt2_tex*wt1], bc ----------------
__global__ void k_prep(const float* __restrict__ wt1, const float* __restrict__ bt1,
                       const float* __restrict__ wt2, const float* __restrict__ bt2) {
    int tid = threadIdx.x;
    for (int i = tid; i < 64*128; i += 256) {
        int o = i >> 7, k = i & 127;
        g_wc[o*256 + k] = wt2[o*192 + k];
    }
    for (int i = tid; i < 64*128; i += 256) {
        int o = i >> 7, j = i & 127;
        float s = 0.f;
        for (int m = 0; m < 64; m++) s += wt2[o*192 + 128 + m] * wt1[m*128 + j];
        g_wc[o*256 + 128 + j] = s;
    }
    if (tid < 64) {
        float s = bt2[tid];
        for (int m = 0; m < 64; m++) s += wt2[tid*192 + 128 + m] * bt1[m];
        g_bc[tid] = s;
    }
}

// ---------------- final fused 1x1 conv over [feature, x, Tcat] (64 x 256) ----------------
// grid (16 pixel-chunks, 4 oc-quarters, BB)
__global__ void __launch_bounds__(256) k_final2(const float* __restrict__ x,
                                                float* __restrict__ out) {
    __shared__ float s_w[16*64];
    int b = blockIdx.z;
    int oc0 = blockIdx.y * 16;
    int p = blockIdx.x*256 + threadIdx.x;
    float acc[16];
    #pragma unroll
    for (int o = 0; o < 16; o++) acc[o] = g_bc[oc0 + o];

    const float* srcs[4] = {
        &g_feat[(size_t)b*64*L],
        x + (size_t)b*64*L,
        &g_Tcat[(size_t)(b*2 + 0)*C*L],
        &g_Tcat[(size_t)(b*2 + 1)*C*L] };
    for (int g = 0; g < 4; g++) {
        __syncthreads();
        for (int i = threadIdx.x; i < 16*64; i += 256) {
            int o = i >> 6, k = i & 63;
            s_w[i] = g_wc[(oc0 + o)*256 + g*64 + k];
        }
        __syncthreads();
        const float* in = srcs[g];
        for (int k = 0; k < 64; k++) {
            float v = in[k*L + p];
            #pragma unroll
            for (int o = 0; o < 16; o++) acc[o] += v * s_w[o*64 + k];
        }
    }
    #pragma unroll
    for (int o = 0; o < 16; o++) out[((size_t)b*64 + oc0 + o)*L + p] = acc[o];
}

// ---------------- lazy stream/event resources (CPU-side only; no device alloc) ----------------
static cudaStream_t side_stream() {
    static cudaStream_t s = nullptr;
    if (!s) cudaStreamCreateWithFlags(&s, cudaStreamNonBlocking);
    return s;
}
static cudaEvent_t ev_fork() {
    static cudaEvent_t e = nullptr;
    if (!e) cudaEventCreateWithFlags(&e, cudaEventDisableTiming);
    return e;
}
static cudaEvent_t ev_join() {
    static cudaEvent_t e = nullptr;
    if (!e) cudaEventCreateWithFlags(&e, cudaEventDisableTiming);
    return e;
}

// ---------------- host launcher (graph-capturable, 2 streams) ----------------
extern "C" void kernel_launch(void* const* d_in, const int* in_sizes, int n_in,
                              void* d_out, int out_size) {
    const float* x   = (const float*)d_in[0];
    const float* w1  = (const float*)d_in[1];
    const float* b1  = (const float*)d_in[2];
    const float* w2  = (const float*)d_in[3];
    const float* b2  = (const float*)d_in[4];
    const float* wt1 = (const float*)d_in[5];
    const float* bt1 = (const float*)d_in[6];
    const float* wt2 = (const float*)d_in[7];
    const float* bt2 = (const float*)d_in[8];
    float* out = (float*)d_out;

    cudaFuncSetAttribute(k_gram_sym, cudaFuncAttributeMaxDynamicSharedMemorySize, SMEM_REQ);

    cudaStream_t s1 = side_stream();
    cudaEvent_t eF = ev_fork(), eJ = ev_join();

    // fork: side stream runs convs + weight prep (depend only on inputs)
    cudaEventRecord(eF, 0);
    cudaStreamWaitEvent(s1, eF, 0);
    k_conv3x3<<<dim3(16, 4, BB), 256, 0, s1>>>(x, w1, b1, 1, 0, 0);
    k_conv3x3<<<dim3(16, 4, BB), 256, 0, s1>>>(x, w2, b2, 0, 1, 1);
    k_prep<<<1, 256, 0, s1>>>(wt1, bt1, wt2, bt2);
    cudaEventRecord(eJ, s1);

    // main chain: pad -> norms -> split -> gram -> merge -> fold
    k_xpad<<<(BB*C*HP*HP + 255)/256, 256>>>(x);
    k_n2<<<(BB*HP*HP*8 + 255)/256, 256>>>();
    k_rnorm<<<(BB*L + 255)/256, 256>>>();
    k_unsplit<<<(BB*L*(F/2) + 255)/256, 256>>>();
    k_gram_sym<<<dim3(NTASKP, BB), 256, SMEM_REQ>>>();
    k_merge64<<<(BB*L*8 + 255)/256, 256>>>();
    k_fold<<<dim3(32, 2, BB), 256>>>();

    // join: final conv needs g_feat (s1) + g_Tcat/g_wc
    cudaStreamWaitEvent(0, eJ, 0);
    k_final2<<<dim3(16, 4, BB), 256>>>(x, out);
}

// round 17
// speedup vs baseline: 1.4990x; 1.4990x over previous
#include <cuda_runtime.h>
#include <cuda_fp16.h>
#include <cmath>
#include <cstdint>

#define BB 2
#define C 64
#define H 64
#define W 64
#define L 4096   // H*W
#define F 576    // C*9
#define HP 66    // H+2

#define NCH 36                    // 576/16 k16-chunks
#define NBLK 64                   // 64 key/query blocks of 64
#define NTASK (NBLK*(NBLK+1)/2)   // 2080 tiles per batch

#define ROWP 48                   // 32B data + 16B pad: conflict-free LDSM
#define TILE64 (64*ROWP)          // 3072
#define STAGE (4*TILE64)          // 12288 (A-s0, A-s1, B-s0, B-s1)
#define NSTG 4
#define SMEM_REQ (NSTG*STAGE)     // 49152 -> 4 CTAs/SM

// ---------------- scratch ----------------
__device__ float g_xcl[BB*HP*HP*C];      // [b][y][x][c] channels-last reflect-padded
__device__ float g_n2[BB*HP*HP];         // per-pixel channel sum of squares
__device__ float g_h1[BB*C*L];
__device__ float g_feat[BB*C*L];
__device__ float g_rnorm[BB*L];
__device__ __half g_p0[BB*L*F];          // [b][q][f'] fp16 split hi (f' = k*64+c)
__device__ __half g_p1[BB*L*F];          // fp16 split lo
__device__ float g_pv[BB*NBLK*3*L];      // partial top-3 values: [b][slot][e][q]
__device__ int   g_pi[BB*NBLK*3*L];      // partial top-3 indices
__device__ float g_tv[BB*L*3];
__device__ int   g_ti[BB*L*3];
__device__ float g_Tcat[BB*2*C*L];
__device__ float g_wc[64*256];           // combined final weights
__device__ float g_bc[64];               // combined final bias

// ---------------- PTX helpers (baseline ISA) ----------------
__device__ __forceinline__ uint32_t s2u(const void* p) {
    uint32_t a;
    asm("{ .reg .u64 t; cvta.to.shared.u64 t, %1; cvt.u32.u64 %0, t; }" : "=r"(a) : "l"(p));
    return a;
}
#define CPA16(d, s) asm volatile("cp.async.cg.shared.global [%0], [%1], 16;" :: "r"(d), "l"(s))
#define CPCOMMIT()  asm volatile("cp.async.commit_group;" ::: "memory")
#define CPWAIT2()   asm volatile("cp.async.wait_group 2;" ::: "memory")
#define CPWAIT1()   asm volatile("cp.async.wait_group 1;" ::: "memory")
#define CPWAIT0()   asm volatile("cp.async.wait_group 0;" ::: "memory")
#define LDSM_X4(r, addr) asm volatile("ldmatrix.sync.aligned.m8n8.x4.shared.b16 {%0,%1,%2,%3}, [%4];" \
    : "=r"((r)[0]), "=r"((r)[1]), "=r"((r)[2]), "=r"((r)[3]) : "r"(addr))
#define MMAF16(c, a, b0, b1) \
    asm volatile("mma.sync.aligned.m16n8k16.row.col.f32.f16.f16.f32 " \
        "{%0,%1,%2,%3}, {%4,%5,%6,%7}, {%8,%9}, {%0,%1,%2,%3};" \
        : "+f"((c)[0]), "+f"((c)[1]), "+f"((c)[2]), "+f"((c)[3]) \
        : "r"((a)[0]), "r"((a)[1]), "r"((a)[2]), "r"((a)[3]), "r"(b0), "r"(b1))

// total order: larger value first, ties -> smaller index (lax.top_k)
__device__ __forceinline__ bool bet(float va, int ia, float vb, int ib) {
    return (va > vb) || (va == vb && ia < ib);
}
__device__ __forceinline__ void ins3(float v, int i,
                                     float& v0, int& i0, float& v1, int& i1,
                                     float& v2, int& i2) {
    if (bet(v, i, v2, i2)) {
        if (bet(v, i, v0, i0))      { v2=v1;i2=i1; v1=v0;i1=i0; v0=v;i0=i; }
        else if (bet(v, i, v1, i1)) { v2=v1;i2=i1; v1=v;i1=i; }
        else                        { v2=v;i2=i; }
    }
}

// ---------------- reflect pad (channels-last) ----------------
__global__ void k_xpad(const float* __restrict__ x) {
    int idx = blockIdx.x * blockDim.x + threadIdx.x;
    const int total = BB*C*HP*HP;
    if (idx >= total) return;
    int xx = idx % HP; int t = idx / HP;
    int yy = t % HP;   t /= HP;
    int c  = t % C;    int b = t / C;
    int sy = yy - 1; sy = sy < 0 ? -sy : (sy > H-1 ? 2*(H-1)-sy : sy);
    int sx = xx - 1; sx = sx < 0 ? -sx : (sx > W-1 ? 2*(W-1)-sx : sx);
    g_xcl[((b*HP + yy)*HP + xx)*C + c] = x[((b*C + c)*H + sy)*W + sx];
}

// ---------------- per-pixel channel sum-of-squares (8 lanes per pixel) ----------------
__global__ void k_n2() {
    int idx = blockIdx.x * blockDim.x + threadIdx.x;
    if (idx >= BB*HP*HP*8) return;
    int pix = idx >> 3, l8 = idx & 7;
    const float4* p = (const float4*)(g_xcl + (size_t)pix*C + l8*8);
    float4 a = p[0], c = p[1];
    float s = a.x*a.x + a.y*a.y + a.z*a.z + a.w*a.w
            + c.x*c.x + c.y*c.y + c.z*c.z + c.w*c.w;
    s += __shfl_xor_sync(0xffffffffu, s, 1);
    s += __shfl_xor_sync(0xffffffffu, s, 2);
    s += __shfl_xor_sync(0xffffffffu, s, 4);
    if (l8 == 0) g_n2[pix] = s;
}

// ---------------- patch rnorm from 3x3 window of n2 ----------------
__global__ void k_rnorm() {
    int idx = blockIdx.x * blockDim.x + threadIdx.x;
    if (idx >= BB*L) return;
    int b = idx / L, q = idx % L;
    int qy = q >> 6, qx = q & 63;
    const float* n2 = g_n2 + b*HP*HP;
    float s = 0.f;
    #pragma unroll
    for (int i = 0; i < 3; i++)
        #pragma unroll
        for (int j = 0; j < 3; j++)
            s += n2[(qy + i)*HP + qx + j];
    g_rnorm[idx] = 1.f / fmaxf(sqrtf(s), 1e-12f);
}

// ---------------- normalized unfold, fp16 2-way split, half2-vectorized ----------------
__global__ void k_unsplit() {
    int idx = blockIdx.x * blockDim.x + threadIdx.x;
    if (idx >= BB*L*(F/2)) return;
    int f2 = idx % (F/2); int t = idx / (F/2);
    int q = t % L;        int b = t / L;
    int f = f2 * 2;
    int k = f >> 6, c = f & 63;       // c even; c,c+1 share k
    int i = k / 3, j = k % 3;
    int qy = q >> 6, qx = q & 63;
    float rn = g_rnorm[b*L + q];
    const float2 xv = *(const float2*)(g_xcl + ((size_t)((b*HP + qy + i)*HP + qx + j))*C + c);
    float va = xv.x * rn, vb = xv.y * rn;
    __half ha0 = __float2half_rn(va), hb0 = __float2half_rn(vb);
    __half ha1 = __float2half_rn(va - __half2float(ha0));
    __half hb1 = __float2half_rn(vb - __half2float(hb0));
    size_t o = (size_t)b*L*F + (size_t)q*F + f;
    *(__half2*)(g_p0 + o) = __halves2half2(ha0, hb0);
    *(__half2*)(g_p1 + o) = __halves2half2(ha1, hb1);
}

// ---------------- symmetric fp16 HMMA Gram: one 64x64 tile (j>=i) per CTA ----------------
// grid (2080) per batch, 128 threads (4 warps), 4 CTAs/SM, k16 chunks, 4-stage pipeline.
__global__ void __launch_bounds__(128, 4) k_gram_sym(int b) {
    extern __shared__ char smem[];
    const uint32_t sb = s2u(smem);

    const int tid = threadIdx.x;
    const int w = tid >> 5, lane = tid & 31;

    // decode upper-triangular tile (i,j), j>=i
    int t = blockIdx.x;
    int i = (int)((129.0 - sqrt(129.0*129.0 - 8.0*(double)t)) * 0.5);
    while ((i+1)*NBLK - ((i+1)*i)/2 <= t) i++;
    while (i*NBLK - (i*(i-1))/2 > t) i--;
    const int j = i + (t - (i*NBLK - (i*(i-1))/2));
    const int q0 = i*64, n0 = j*64;

    const __half* P0 = g_p0 + (size_t)b*L*F;
    const __half* P1 = g_p1 + (size_t)b*L*F;

    const int warpRow = (w >> 1) * 32;   // 0 or 32
    const int warpCol = (w & 1) * 32;    // 0 or 32
    const uint32_t aofs = (uint32_t)((warpRow + (lane & 15))*ROWP + (lane >> 4)*16);
    const uint32_t bofs = (uint32_t)(2*TILE64
                          + (warpCol + ((lane >> 4) & 1)*8 + (lane & 7))*ROWP
                          + ((lane >> 3) & 1)*16);

    // hoisted loader mapping: 4 granules per thread (512 granules = 256 rows x 2)
    const __half* lsrc[4];
    uint32_t ldst[4];
    #pragma unroll
    for (int t4 = 0; t4 < 4; t4++) {
        int g = t4*128 + tid;
        int rr = g >> 1, c = g & 1;
        int reg = rr >> 6, row = rr & 63;
        int grow = (reg < 2 ? q0 : n0) + row;
        lsrc[t4] = ((reg & 1) ? P1 : P0) + (size_t)grow*F + c*8;
        ldst[t4] = (uint32_t)(rr*ROWP + c*16);
    }

    float acc[2][4][4];
    #pragma unroll
    for (int mf = 0; mf < 2; mf++)
        #pragma unroll
        for (int nf = 0; nf < 4; nf++)
            #pragma unroll
            for (int e = 0; e < 4; e++) acc[mf][nf][e] = 0.f;

    #define ISSUE(pc) do {                                                      \
        int _f0 = (pc) * 16;                                                    \
        uint32_t _st = sb + ((pc) & 3) * STAGE;                                 \
        CPA16(_st + ldst[0], lsrc[0] + _f0);                                    \
        CPA16(_st + ldst[1], lsrc[1] + _f0);                                    \
        CPA16(_st + ldst[2], lsrc[2] + _f0);                                    \
        CPA16(_st + ldst[3], lsrc[3] + _f0);                                    \
        CPCOMMIT();                                                             \
    } while (0)

    ISSUE(0); ISSUE(1); ISSUE(2);

    for (int ck = 0; ck < NCH; ck++) {
        if (ck < NCH-2)       { CPWAIT2(); }
        else if (ck == NCH-2) { CPWAIT1(); }
        else                  { CPWAIT0(); }
        __syncthreads();
        if (ck + 3 < NCH) ISSUE(ck + 3);

        const uint32_t stage = sb + (ck & 3) * STAGE;

        // load ALL fragments first
        uint32_t afr[2][2][4];   // [split][mf]
        #pragma unroll
        for (int sp = 0; sp < 2; sp++)
            #pragma unroll
            for (int mf = 0; mf < 2; mf++)
                LDSM_X4(afr[sp][mf], stage + sp*TILE64 + aofs + mf*(16*ROWP));
        uint32_t bfr[2][2][4];   // [split][nfp]
        #pragma unroll
        for (int sp = 0; sp < 2; sp++)
            #pragma unroll
            for (int nfp = 0; nfp < 2; nfp++)
                LDSM_X4(bfr[sp][nfp], stage + sp*TILE64 + bofs + nfp*(16*ROWP));

        // 3 split-term passes over all 8 distinct accumulators
        #pragma unroll
        for (int mf = 0; mf < 2; mf++)
            #pragma unroll
            for (int nfp = 0; nfp < 2; nfp++)
                #pragma unroll
                for (int nn = 0; nn < 2; nn++)
                    MMAF16(acc[mf][nfp*2+nn], afr[0][mf], bfr[0][nfp][nn*2], bfr[0][nfp][nn*2+1]);
        #pragma unroll
        for (int mf = 0; mf < 2; mf++)
            #pragma unroll
            for (int nfp = 0; nfp < 2; nfp++)
                #pragma unroll
                for (int nn = 0; nn < 2; nn++)
                    MMAF16(acc[mf][nfp*2+nn], afr[1][mf], bfr[0][nfp][nn*2], bfr[0][nfp][nn*2+1]);
        #pragma unroll
        for (int mf = 0; mf < 2; mf++)
            #pragma unroll
            for (int nfp = 0; nfp < 2; nfp++)
                #pragma unroll
                for (int nn = 0; nn < 2; nn++)
                    MMAF16(acc[mf][nfp*2+nn], afr[0][mf], bfr[1][nfp][nn*2], bfr[1][nfp][nn*2+1]);
    }
    #undef ISSUE

    // ---- epilogue: tile -> smem, fold rows (block i) and cols (block j) ----
    float* Ct = (float*)smem;    // [64][65] padded (16640 B, aliases stages)
    __syncthreads();
    #pragma unroll
    for (int mf = 0; mf < 2; mf++)
        #pragma unroll
        for (int nf = 0; nf < 4; nf++)
            #pragma unroll
            for (int e = 0; e < 4; e++) {
                int r = warpRow + mf*16 + (e >> 1)*8 + (lane >> 2);
                int c = warpCol + nf*8 + (lane & 3)*2 + (e & 1);
                Ct[r*65 + c] = acc[mf][nf][e];
            }
    __syncthreads();

    float v0 = -2.f, v1 = -2.f, v2 = -2.f;
    int   i0 = 0x7fffffff, i1 = 0x7fffffff, i2 = 0x7fffffff;
    if (tid < 64) {
        int r = tid;
        #pragma unroll 8
        for (int c = 0; c < 64; c++)
            ins3(Ct[r*65 + c], n0 + c, v0,i0, v1,i1, v2,i2);
        size_t base = ((size_t)(b*NBLK + j)*3)*L + (q0 + r);
        g_pv[base]       = v0; g_pv[base + L]   = v1; g_pv[base + 2*L] = v2;
        g_pi[base]       = i0; g_pi[base + L]   = i1; g_pi[base + 2*L] = i2;
    } else if (i != j) {
        int c = tid - 64;
        #pragma unroll 8
        for (int r = 0; r < 64; r++)
            ins3(Ct[r*65 + c], q0 + r, v0,i0, v1,i1, v2,i2);
        size_t base = ((size_t)(b*NBLK + i)*3)*L + (n0 + c);
        g_pv[base]       = v0; g_pv[base + L]   = v1; g_pv[base + 2*L] = v2;
        g_pi[base]       = i0; g_pi[base + L]   = i1; g_pi[base + 2*L] = i2;
    }
}

// ---------------- merge the 64 per-block partial top-3s (per batch) ----------------
// grid (L/32) = 128 blocks, 256 threads: 8 slot-groups x 32 queries.
__global__ void __launch_bounds__(256) k_merge64(int b) {
    __shared__ float sv[8*32*3];
    __shared__ int   si[8*32*3];
    int tid = threadIdx.x;
    int qloc = tid & 31, g = tid >> 5;
    int q = blockIdx.x*32 + qloc;

    float v0 = -2.f, v1 = -2.f, v2 = -2.f;
    int   i0 = 0x7fffffff, i1 = 0x7fffffff, i2 = 0x7fffffff;
    #pragma unroll
    for (int s8 = 0; s8 < 8; s8++) {
        int s = g*8 + s8;
        size_t base = ((size_t)(b*NBLK + s)*3)*L + q;
        float a0 = g_pv[base]; int j0 = g_pi[base];
        if (bet(a0, j0, v2, i2)) {          // partials sorted desc -> short-circuit
            ins3(a0, j0, v0,i0, v1,i1, v2,i2);
            ins3(g_pv[base + L],   g_pi[base + L],   v0,i0, v1,i1, v2,i2);
            ins3(g_pv[base + 2*L], g_pi[base + 2*L], v0,i0, v1,i1, v2,i2);
        }
    }
    int sidx = (g*32 + qloc)*3;
    sv[sidx] = v0; sv[sidx+1] = v1; sv[sidx+2] = v2;
    si[sidx] = i0; si[sidx+1] = i1; si[sidx+2] = i2;
    __syncthreads();
    if (g == 0) {
        #pragma unroll
        for (int gg = 1; gg < 8; gg++) {
            int s2 = (gg*32 + qloc)*3;
            float a0 = sv[s2]; int j0 = si[s2];
            if (bet(a0, j0, v2, i2)) {
                ins3(a0, j0, v0,i0, v1,i1, v2,i2);
                ins3(sv[s2+1], si[s2+1], v0,i0, v1,i1, v2,i2);
                ins3(sv[s2+2], si[s2+2], v0,i0, v1,i1, v2,i2);
            }
        }
        size_t d = (size_t)(b*L + q)*3;
        g_tv[d]   = v0; g_tv[d+1] = v1; g_tv[d+2] = v2;
        g_ti[d]   = i0; g_ti[d+1] = i1; g_ti[d+2] = i2;
    }
}

// ---------------- 3x3 conv (zero pad), optional relu ----------------
__global__ void __launch_bounds__(256) k_conv3x3(
    const float* __restrict__ xin, const float* __restrict__ w,
    const float* __restrict__ bias, int relu, int insel, int outsel)
{
    __shared__ float s_in[16][324];
    __shared__ float s_w[16][144];

    const float* in = insel ? g_h1 : xin;
    float* out = outsel ? g_feat : g_h1;

    int tile = blockIdx.x;
    int oc0  = blockIdx.y * 16;
    int b    = blockIdx.z;
    int ty0 = (tile / 4) * 16, tx0 = (tile % 4) * 16;
    int tid = threadIdx.x;
    int py = tid / 16, px = tid % 16;

    float acc[16];
    #pragma unroll
    for (int o = 0; o < 16; o++) acc[o] = bias[oc0 + o];

    for (int icc = 0; icc < 4; icc++) {
        for (int i = tid; i < 16*324; i += 256) {
            int ic = i / 324; int rem = i % 324;
            int yy = rem / 18, xx = rem % 18;
            int gy = ty0 + yy - 1, gx = tx0 + xx - 1;
            float v = 0.f;
            if (gy >= 0 && gy < H && gx >= 0 && gx < W)
                v = in[((b*C + icc*16 + ic)*H + gy)*W + gx];
            s_in[ic][rem] = v;
        }
        for (int i = tid; i < 16*144; i += 256) {
            int o = i / 144; int rem = i % 144;
            s_w[o][rem] = w[((oc0 + o)*C + icc*16 + rem/9)*9 + rem%9];
        }
        __syncthreads();

        for (int ic = 0; ic < 16; ic++) {
            float v[9];
            #pragma unroll
            for (int dy = 0; dy < 3; dy++)
                #pragma unroll
                for (int dx = 0; dx < 3; dx++)
                    v[dy*3+dx] = s_in[ic][(py+dy)*18 + px+dx];
            #pragma unroll
            for (int o = 0; o < 16; o++) {
                float a = acc[o];
                #pragma unroll
                for (int k = 0; k < 9; k++) a += v[k] * s_w[o][ic*9 + k];
                acc[o] = a;
            }
        }
        __syncthreads();
    }
    int gy = ty0 + py, gx = tx0 + px;
    #pragma unroll
    for (int o = 0; o < 16; o++) {
        float v = acc[o];
        if (relu) v = fmaxf(v, 0.f);
        out[((b*C + oc0 + o)*H + gy)*W + gx] = v;
    }
}

// ---------------- gather + fold3 + scale (per batch; coalesced writes via smem) ----------------
// grid (32 row-pairs, 2 tt), 256 threads.
__global__ void __launch_bounds__(256) k_fold(int b) {
    __shared__ float st[64*128];    // [c][px], 32 KB
    int tile = blockIdx.x;
    int tt   = blockIdx.y;
    int tid  = threadIdx.x;
    int p = tid & 127, ch0 = (tid >> 7) * 32;
    int y = tile*2 + (p >> 6), x = p & 63;
    int q = y*W + x;
    int slot = tt + 1;

    float S = g_tv[(b*L + q)*3 + slot];
    const int bbase = b*HP*HP;

    int off[9];
    #pragma unroll
    for (int i = 0; i < 3; i++) {
        #pragma unroll
        for (int j = 0; j < 3; j++) {
            int h = y + 1 - i, w = x + 1 - j;
            int o = -1;
            if (h >= 0 && h < H && w >= 0 && w < W) {
                int r = g_ti[(b*L + h*W + w)*3 + slot];
                int ry = r >> 6, rx = r & 63;
                o = (bbase + (ry + i)*HP + (rx + j)) * C + ch0;
            }
            off[i*3 + j] = o;
        }
    }

    float4 a4[8];
    #pragma unroll
    for (int r = 0; r < 8; r++) a4[r] = make_float4(0.f, 0.f, 0.f, 0.f);
    #pragma unroll
    for (int k = 0; k < 9; k++) {
        if (off[k] >= 0) {
            const float4* src = (const float4*)(g_xcl + off[k]);
            #pragma unroll
            for (int r = 0; r < 8; r++) {
                float4 v = src[r];
                a4[r].x += v.x; a4[r].y += v.y; a4[r].z += v.z; a4[r].w += v.w;
            }
        }
    }
    float scale = S * (1.f/9.f);
    #pragma unroll
    for (int r = 0; r < 8; r++) {
        st[(ch0 + r*4 + 0)*128 + p] = a4[r].x * scale;
        st[(ch0 + r*4 + 1)*128 + p] = a4[r].y * scale;
        st[(ch0 + r*4 + 2)*128 + p] = a4[r].z * scale;
        st[(ch0 + r*4 + 3)*128 + p] = a4[r].w * scale;
    }
    __syncthreads();
    float* out = &g_Tcat[(size_t)((b*2 + tt)*C)*L + tile*128];
    #pragma unroll
    for (int it = 0; it < 32; it++) {
        int idx2 = it*256 + tid;
        int c = idx2 >> 7, px = idx2 & 127;
        out[(size_t)c*L + px] = st[idx2];
    }
}

// ---------------- fold wt1 into wt2: wc = [wt2_f | wt2_x | wt2_tex*wt1], bc ----------------
__global__ void k_prep(const float* __restrict__ wt1, const float* __restrict__ bt1,
                       const float* __restrict__ wt2, const float* __restrict__ bt2) {
    int tid = threadIdx.x;
    for (int i = tid; i < 64*128; i += 256) {
        int o = i >> 7, k = i & 127;
        g_wc[o*256 + k] = wt2[o*192 + k];
    }
    for (int i = tid; i < 64*128; i += 256) {
        int o = i >> 7, j = i & 127;
        float s = 0.f;
        for (int m = 0; m < 64; m++) s += wt2[o*192 + 128 + m] * wt1[m*128 + j];
        g_wc[o*256 + 128 + j] = s;
    }
    if (tid < 64) {
        float s = bt2[tid];
        for (int m = 0; m < 64; m++) s += wt2[tid*192 + 128 + m] * bt1[m];
        g_bc[tid] = s;
    }
}

// ---------------- final fused 1x1 conv over [feature, x, Tcat] (per batch) ----------------
// grid (16 pixel-chunks, 4 oc-quarters)
__global__ void __launch_bounds__(256) k_final2(const float* __restrict__ x,
                                                float* __restrict__ out, int b) {
    __shared__ float s_w[16*64];
    int oc0 = blockIdx.y * 16;
    int p = blockIdx.x*256 + threadIdx.x;
    float acc[16];
    #pragma unroll
    for (int o = 0; o < 16; o++) acc[o] = g_bc[oc0 + o];

    const float* srcs[4] = {
        &g_feat[(size_t)b*64*L],
        x + (size_t)b*64*L,
        &g_Tcat[(size_t)(b*2 + 0)*C*L],
        &g_Tcat[(size_t)(b*2 + 1)*C*L] };
    for (int g = 0; g < 4; g++) {
        __syncthreads();
        for (int i = threadIdx.x; i < 16*64; i += 256) {
            int o = i >> 6, k = i & 63;
            s_w[i] = g_wc[(oc0 + o)*256 + g*64 + k];
        }
        __syncthreads();
        const float* in = srcs[g];
        for (int k = 0; k < 64; k++) {
            float v = in[k*L + p];
            #pragma unroll
            for (int o = 0; o < 16; o++) acc[o] += v * s_w[o*64 + k];
        }
    }
    #pragma unroll
    for (int o = 0; o < 16; o++) out[((size_t)b*64 + oc0 + o)*L + p] = acc[o];
}

// ---------------- lazy stream/event resources (CPU-side only; no device alloc) ----------------
static cudaStream_t stream_a() {
    static cudaStream_t s = nullptr;
    if (!s) cudaStreamCreateWithFlags(&s, cudaStreamNonBlocking);
    return s;
}
static cudaStream_t stream_b() {
    static cudaStream_t s = nullptr;
    if (!s) cudaStreamCreateWithFlags(&s, cudaStreamNonBlocking);
    return s;
}
static cudaEvent_t mk_event(int which) {
    static cudaEvent_t e[4] = {nullptr, nullptr, nullptr, nullptr};
    if (!e[which]) cudaEventCreateWithFlags(&e[which], cudaEventDisableTiming);
    return e[which];
}

// ---------------- host launcher (graph-capturable, 3 streams) ----------------
extern "C" void kernel_launch(void* const* d_in, const int* in_sizes, int n_in,
                              void* d_out, int out_size) {
    const float* x   = (const float*)d_in[0];
    const float* w1  = (const float*)d_in[1];
    const float* b1  = (const float*)d_in[2];
    const float* w2  = (const float*)d_in[3];
    const float* b2  = (const float*)d_in[4];
    const float* wt1 = (const float*)d_in[5];
    const float* bt1 = (const float*)d_in[6];
    const float* wt2 = (const float*)d_in[7];
    const float* bt2 = (const float*)d_in[8];
    float* out = (float*)d_out;

    cudaFuncSetAttribute(k_gram_sym, cudaFuncAttributeMaxDynamicSharedMemorySize, SMEM_REQ);

    cudaStream_t s1 = stream_a();   // convs + prep
    cudaStream_t s2 = stream_b();   // batch-0 tail
    cudaEvent_t eF  = mk_event(0);  // fork
    cudaEvent_t eJ  = mk_event(1);  // convs+prep done
    cudaEvent_t eG0 = mk_event(2);  // gram(b0) done
    cudaEvent_t eB0 = mk_event(3);  // batch-0 tail done

    // fork: side stream runs convs + weight prep (depend only on inputs)
    cudaEventRecord(eF, 0);
    cudaStreamWaitEvent(s1, eF, 0);
    k_conv3x3<<<dim3(16, 4, BB), 256, 0, s1>>>(x, w1, b1, 1, 0, 0);
    k_conv3x3<<<dim3(16, 4, BB), 256, 0, s1>>>(x, w2, b2, 0, 1, 1);
    k_prep<<<1, 256, 0, s1>>>(wt1, bt1, wt2, bt2);
    cudaEventRecord(eJ, s1);

    // main chain: pad -> norms -> split -> gram(b0) -> gram(b1)
    k_xpad<<<(BB*C*HP*HP + 255)/256, 256>>>(x);
    k_n2<<<(BB*HP*HP*8 + 255)/256, 256>>>();
    k_rnorm<<<(BB*L + 255)/256, 256>>>();
    k_unsplit<<<(BB*L*(F/2) + 255)/256, 256>>>();
    k_gram_sym<<<NTASK, 128, SMEM_REQ>>>(0);
    cudaEventRecord(eG0, 0);
    k_gram_sym<<<NTASK, 128, SMEM_REQ>>>(1);

    // batch-0 tail on s2, overlapping gram(b1)
    cudaStreamWaitEvent(s2, eG0, 0);
    k_merge64<<<L/32, 256, 0, s2>>>(0);
    k_fold<<<dim3(32, 2), 256, 0, s2>>>(0);
    cudaStreamWaitEvent(s2, eJ, 0);
    k_final2<<<dim3(16, 4), 256, 0, s2>>>(x, out, 0);
    cudaEventRecord(eB0, s2);

    // batch-1 tail on default stream (after gram(b1))
    k_merge64<<<L/32, 256>>>(1);
    k_fold<<<dim3(32, 2), 256>>>(1);
    cudaStreamWaitEvent(0, eJ, 0);
    k_final2<<<dim3(16, 4), 256>>>(x, out, 1);

    // join batch-0 tail back into the origin stream
    cudaStreamWaitEvent(0, eB0, 0);
}